// round 12
// baseline (speedup 1.0000x reference)
#include <cuda_runtime.h>
#include <cuda_fp16.h>
#include <cstdint>

// Problem constants
#define BSZ 4
#define LEN 2048
#define NH  12
#define HD  64
#define RR  16
#define HID 768
#define MM  (BSZ*LEN)   // 8192
#define NN  (NH*HD)     // 768
#define KK  HID         // 768

// ---------------------------------------------------------------------------
// Scratch (__device__ globals; allocation is forbidden)
// ---------------------------------------------------------------------------
__device__ __align__(16) __half g_Ahi[(size_t)MM * KK];
__device__ __align__(16) __half g_Alo[(size_t)MM * KK];
__device__ __align__(16) __half g_WhiK[(size_t)NN * KK];   // [n][k]
__device__ __align__(16) __half g_WloK[(size_t)NN * KK];
__device__ __align__(16) __half g_WhiV[(size_t)NN * KK];   // V: hi only (2-pass)
__device__ __align__(16) float g_V1[(size_t)MM * NN];
__device__ __align__(16) float g_dot[(size_t)MM * NH];
__device__ __align__(16) int   g_fm[(size_t)MM * NH * RR];
__device__ __align__(16) int   g_bm[(size_t)MM * NH * RR];

// ---------------------------------------------------------------------------
// Baseline-PTX helpers (sm_80+: mma.sync / ldmatrix / cp.async — NO tcgen05)
// ---------------------------------------------------------------------------
__device__ __forceinline__ uint32_t smem_u32(const void* p) {
    uint32_t a;
    asm("{ .reg .u64 t; cvta.to.shared.u64 t, %1; cvt.u32.u64 %0, t; }"
        : "=r"(a) : "l"(p));
    return a;
}

__device__ __forceinline__ void cp16(uint32_t dst, const void* src) {
    asm volatile("cp.async.cg.shared.global [%0], [%1], 16;"
                 :: "r"(dst), "l"(src));
}
__device__ __forceinline__ void cp_commit() {
    asm volatile("cp.async.commit_group;");
}
template<int N> __device__ __forceinline__ void cp_wait() {
    asm volatile("cp.async.wait_group %0;" :: "n"(N));
}

__device__ __forceinline__ void ldsm4(uint32_t* r, uint32_t addr) {
    asm volatile("ldmatrix.sync.aligned.m8n8.x4.shared.b16 {%0,%1,%2,%3}, [%4];"
                 : "=r"(r[0]), "=r"(r[1]), "=r"(r[2]), "=r"(r[3]) : "r"(addr));
}

__device__ __forceinline__ void mma16816(float* c, const uint32_t* a,
                                         uint32_t b0, uint32_t b1) {
    asm volatile(
        "mma.sync.aligned.m16n8k16.row.col.f32.f16.f16.f32 "
        "{%0,%1,%2,%3}, {%4,%5,%6,%7}, {%8,%9}, {%0,%1,%2,%3};"
        : "+f"(c[0]), "+f"(c[1]), "+f"(c[2]), "+f"(c[3])
        : "r"(a[0]), "r"(a[1]), "r"(a[2]), "r"(a[3]), "r"(b0), "r"(b1));
}

// XOR-swizzled smem address: 128B rows, 16B segments, seg ^= (row & 7)
__device__ __forceinline__ uint32_t swz(int row, int seg) {
    return (uint32_t)(row * 128 + (((seg) ^ (row & 7)) << 4));
}

// ---------------------------------------------------------------------------
// Split-conversion kernels (fp32 -> fp16 hi + fp16 lo)
// ---------------------------------------------------------------------------
__device__ __forceinline__ uint32_t pack_h2(__half a, __half b) {
    return ((uint32_t)__half_as_ushort(b) << 16) | (uint32_t)__half_as_ushort(a);
}

__global__ __launch_bounds__(256) void convA_kernel(const float* __restrict__ A) {
    size_t i = ((size_t)blockIdx.x * 256 + threadIdx.x) * 4;
    float4 v = *(const float4*)(A + i);
    __half h0 = __float2half(v.x), h1 = __float2half(v.y);
    __half h2 = __float2half(v.z), h3 = __float2half(v.w);
    __half l0 = __float2half(v.x - __half2float(h0));
    __half l1 = __float2half(v.y - __half2float(h1));
    __half l2 = __float2half(v.z - __half2float(h2));
    __half l3 = __float2half(v.w - __half2float(h3));
    uint2 ph = make_uint2(pack_h2(h0, h1), pack_h2(h2, h3));
    uint2 pl = make_uint2(pack_h2(l0, l1), pack_h2(l2, l3));
    *(uint2*)((char*)g_Ahi + i * 2) = ph;
    *(uint2*)((char*)g_Alo + i * 2) = pl;
}

// Transpose W [k][n] -> [n][k], split hi/lo. WHICH==0 -> K (hi+lo), 1 -> V (hi).
template<int WHICH>
__global__ void convW_kernel(const float* __restrict__ W) {
    __shared__ float t[32][33];
    int bx = blockIdx.x * 32;  // n tile
    int by = blockIdx.y * 32;  // k tile
    int tx = threadIdx.x, ty = threadIdx.y;
#pragma unroll
    for (int j = 0; j < 4; j++) {
        int r = ty + j * 8;
        t[r][tx] = W[(size_t)(by + r) * NN + bx + tx];
    }
    __syncthreads();
#pragma unroll
    for (int j = 0; j < 4; j++) {
        int r = ty + j * 8;
        float x = t[tx][r];  // = W[by+tx][bx+r]
        __half h = __float2half(x);
        size_t o = (size_t)(bx + r) * KK + by + tx;
        if (WHICH == 0) {
            g_WhiK[o] = h;
            g_WloK[o] = __float2half(x - __half2float(h));
        } else {
            g_WhiV[o] = h;
        }
    }
}

// ---------------------------------------------------------------------------
// FUSED mma.sync GEMM, fp16 split, SMSP-balanced asymmetric passes:
//   wids 0-3 -> K head (3 passes: hh + lh + hl) -> dot with RH -> g_dot
//   wids 4-7 -> V head (2 passes: hh + lh)      -> g_V1
// SMSP i hosts wid i (K) and wid i+4 (V) -> every SMSP carries 3+2=5 passes.
// BM=64, BN=128, BK=64. 256 threads, warp tile 32x32 (per half: 2m x 2n).
// 2-stage double buffer, 96KB/CTA -> 2 CTAs/SM.
// ---------------------------------------------------------------------------
#define OFF_AH 0
#define OFF_AL 8192
#define OFF_BH 16384
#define OFF_BL 32768        // only rows 0-63 (K cols) written/read
#define STAGE  49152
#define NSTAGE 2
#define SM_TOTAL (NSTAGE * STAGE)   // 96 KB
#define NCHUNK (KK / 64)            // 12

__global__ __launch_bounds__(256, 2) void fused_gemm_kernel(
    const float* __restrict__ Kb, const float* __restrict__ Vb,
    const float* __restrict__ RH)
{
    extern __shared__ char smem[];
    __shared__ float sdot[64];
    const uint32_t sb = smem_u32(smem);

    const int tid = threadIdx.x;
    const int lane = tid & 31;
    const int wid = tid >> 5;
    const bool is_k = (wid < 4);      // wids 0-3: K half, 4-7: V half
    const int sub = wid & 3;          // == SMSP id
    const int mw = sub >> 1;          // m warp row (0-1, 32 rows each)
    const int nwl = sub & 1;          // n warp col within head (0-1, 32 cols)
    const int bbase = is_k ? 0 : 64;  // B smem row base for this half

    const int head = blockIdx.x;
    const int n0 = head * 64;
    const int m0 = blockIdx.y * 64;

    if (tid < 64) sdot[tid] = 0.f;   // visible by first loop barrier

    float acc[2][4][4];
#pragma unroll
    for (int i = 0; i < 2; i++)
#pragma unroll
        for (int j = 0; j < 4; j++)
#pragma unroll
            for (int q = 0; q < 4; q++) acc[i][j][q] = 0.f;

    auto load_chunk = [&](int c) {
        if (c < NCHUNK) {
            const int kt = c * 64;
            const uint32_t stb = sb + (c & 1) * STAGE;
            // A: 64 rows x 8 segs = 512 positions, hi+lo
#pragma unroll
            for (int i = 0; i < 2; i++) {
                int p = tid + i * 256;
                int row = p >> 3, seg = p & 7;
                uint32_t so = swz(row, seg);
                size_t ga = (size_t)(m0 + row) * KK + kt + seg * 8;
                cp16(stb + OFF_AH + so, g_Ahi + ga);
                cp16(stb + OFF_AL + so, g_Alo + ga);
            }
            // B hi: 128 rows (0-63 K, 64-127 V)
#pragma unroll
            for (int i = 0; i < 4; i++) {
                int p = tid + i * 256;
                int row = p >> 3, seg = p & 7;
                uint32_t so = swz(row, seg);
                const __half* src = (row < 64) ? g_WhiK : g_WhiV;
                int grow = n0 + (row & 63);
                cp16(stb + OFF_BH + so, src + (size_t)grow * KK + kt + seg * 8);
            }
            // B lo: K rows only (rows 0-63)
#pragma unroll
            for (int i = 0; i < 2; i++) {
                int p = tid + i * 256;
                int row = p >> 3, seg = p & 7;
                uint32_t so = swz(row, seg);
                cp16(stb + OFF_BL + so,
                     g_WloK + (size_t)(n0 + row) * KK + kt + seg * 8);
            }
        }
        cp_commit();
    };

    load_chunk(0);

    for (int c = 0; c < NCHUNK; c++) {
        load_chunk(c + 1);          // into stage (c+1)&1 (freed by prev trailing barrier)
        cp_wait<1>();               // stage c complete
        __syncthreads();

        const uint32_t stb = sb + (c & 1) * STAGE;
#pragma unroll
        for (int ks = 0; ks < 4; ks++) {
            uint32_t ah[2][4], al[2][4], bh[2][4], bl[2][4];
#pragma unroll
            for (int mi = 0; mi < 2; mi++) {
                int row = mw * 32 + mi * 16 + (lane & 15);
                int seg = ks * 2 + (lane >> 4);
                uint32_t ao = swz(row, seg);
                ldsm4(ah[mi], stb + OFF_AH + ao);
                ldsm4(al[mi], stb + OFF_AL + ao);
            }
#pragma unroll
            for (int nt = 0; nt < 2; nt++) {
                int row = bbase + nwl * 32 + nt * 16 + (lane & 7) + ((lane >> 4) << 3);
                int seg = ks * 2 + ((lane >> 3) & 1);
                uint32_t bo = swz(row, seg);
                ldsm4(bh[nt], stb + OFF_BH + bo);
            }
            if (is_k) {     // warp-uniform: only K warps need B-lo
#pragma unroll
                for (int nt = 0; nt < 2; nt++) {
                    int row = nwl * 32 + nt * 16 + (lane & 7) + ((lane >> 4) << 3);
                    int seg = ks * 2 + ((lane >> 3) & 1);
                    uint32_t bo = swz(row, seg);
                    ldsm4(bl[nt], stb + OFF_BL + bo);
                }
            }
            // Pass 1: ah * bh (8 independent HMMAs)
#pragma unroll
            for (int mi = 0; mi < 2; mi++)
#pragma unroll
                for (int nj = 0; nj < 4; nj++) {
                    const int nt = nj >> 1, rb = (nj & 1) * 2;
                    mma16816(acc[mi][nj], ah[mi], bh[nt][rb], bh[nt][rb + 1]);
                }
            // Pass 2: al * bh
#pragma unroll
            for (int mi = 0; mi < 2; mi++)
#pragma unroll
                for (int nj = 0; nj < 4; nj++) {
                    const int nt = nj >> 1, rb = (nj & 1) * 2;
                    mma16816(acc[mi][nj], al[mi], bh[nt][rb], bh[nt][rb + 1]);
                }
            // Pass 3 (K warps only): ah * bl
            if (is_k) {
#pragma unroll
                for (int mi = 0; mi < 2; mi++)
#pragma unroll
                    for (int nj = 0; nj < 4; nj++) {
                        const int nt = nj >> 1, rb = (nj & 1) * 2;
                        mma16816(acc[mi][nj], ah[mi], bl[nt][rb], bl[nt][rb + 1]);
                    }
            }
        }
        __syncthreads();   // stage c free before load(c+2) overwrites it
    }

    // ---- epilogue ----
    const int rrow = lane >> 2;
    const int cq = (lane & 3) * 2;

    if (is_k) {
        // K path: dot(relu(K1 + Kb), RH) per row
#pragma unroll
        for (int mi = 0; mi < 2; mi++) {
            float s0 = 0.f, s1 = 0.f;
#pragma unroll
            for (int nj = 0; nj < 4; nj++) {
                const int n = n0 + nwl * 32 + nj * 8 + cq;
                const float b0v = Kb[n], b1v = Kb[n + 1];
                const float rh0 = RH[n], rh1 = RH[n + 1];
                s0 += fmaxf(acc[mi][nj][0] + b0v, 0.f) * rh0
                    + fmaxf(acc[mi][nj][1] + b1v, 0.f) * rh1;
                s1 += fmaxf(acc[mi][nj][2] + b0v, 0.f) * rh0
                    + fmaxf(acc[mi][nj][3] + b1v, 0.f) * rh1;
            }
            s0 += __shfl_xor_sync(0xffffffffu, s0, 1);
            s0 += __shfl_xor_sync(0xffffffffu, s0, 2);
            s1 += __shfl_xor_sync(0xffffffffu, s1, 1);
            s1 += __shfl_xor_sync(0xffffffffu, s1, 2);
            if ((lane & 3) == 0) {
                atomicAdd(&sdot[mw * 32 + mi * 16 + rrow], s0);
                atomicAdd(&sdot[mw * 32 + mi * 16 + rrow + 8], s1);
            }
        }
    } else {
        // V path: store relu(V1 + Vb)
#pragma unroll
        for (int mi = 0; mi < 2; mi++) {
            const int r0 = m0 + mw * 32 + mi * 16 + rrow;
#pragma unroll
            for (int nj = 0; nj < 4; nj++) {
                const int n = n0 + nwl * 32 + nj * 8 + cq;
                const float b0v = Vb[n], b1v = Vb[n + 1];
                float2 v0, v1;
                v0.x = fmaxf(acc[mi][nj][0] + b0v, 0.f);
                v0.y = fmaxf(acc[mi][nj][1] + b1v, 0.f);
                v1.x = fmaxf(acc[mi][nj][2] + b0v, 0.f);
                v1.y = fmaxf(acc[mi][nj][3] + b1v, 0.f);
                *(float2*)&g_V1[(size_t)r0 * NN + n] = v0;
                *(float2*)&g_V1[(size_t)(r0 + 8) * NN + n] = v1;
            }
        }
    }
    __syncthreads();
    if (tid < 64)
        g_dot[(size_t)(m0 + tid) * NH + head] = sdot[tid];
}

// ---------------------------------------------------------------------------
// Scan kernel (per (b,h)): prefix-count + event list -> fm/bm index tables
// (R6-proven version, unchanged)
// ---------------------------------------------------------------------------
__global__ __launch_bounds__(256) void scan_kernel()
{
    const int bh = blockIdx.x;
    const int b = bh / NH, h = bh % NH;

    __shared__ int s_cnt[LEN];
    __shared__ int s_e[LEN];
    __shared__ int s_wsum[8];

    const int tid = threadIdx.x;
    const int base = tid * 8;

    int c[8];
    unsigned mbits = 0;
    int run = 0;
#pragma unroll
    for (int q = 0; q < 8; q++) {
        int l = base + q;
        bool m = (l >= 1) && (g_dot[(size_t)(b * LEN + l) * NH + h] > 0.5f);
        if (m) { mbits |= 1u << q; run++; }
        c[q] = run;
    }

    const int lane = tid & 31, wd = tid >> 5;
    int v = run;
#pragma unroll
    for (int o = 1; o < 32; o <<= 1) {
        int nv = __shfl_up_sync(0xffffffffu, v, o);
        if (lane >= o) v += nv;
    }
    if (lane == 31) s_wsum[wd] = v;
    __syncthreads();
    int wpre = 0;
    for (int w = 0; w < wd; w++) wpre += s_wsum[w];
    const int excl = wpre + v - run;

#pragma unroll
    for (int q = 0; q < 8; q++) {
        s_cnt[base + q] = excl + c[q];
        if (mbits & (1u << q)) s_e[excl + c[q] - 1] = base + q;
    }
    __syncthreads();

    const int E = s_cnt[LEN - 1];

    for (int l = tid; l < LEN; l += 256) {
        int cl = s_cnt[l];
        int cp = (l > 0) ? s_cnt[l - 1] : 0;
        int fo[RR], bo[RR];
#pragma unroll
        for (int r = 0; r < RR; r++) {
            fo[r] = (cl > r) ? s_e[cl - 1 - r] : 0;
            bo[r] = (l > 0 && cp + r < E) ? s_e[cp + r] : 0;
        }
        size_t off = ((size_t)(b * LEN + l) * NH + h) * RR;
#pragma unroll
        for (int r4 = 0; r4 < RR; r4 += 4) {
            *(int4*)&g_fm[off + r4] = make_int4(fo[r4], fo[r4+1], fo[r4+2], fo[r4+3]);
            *(int4*)&g_bm[off + r4] = make_int4(bo[r4], bo[r4+1], bo[r4+2], bo[r4+3]);
        }
    }
}

// ---------------------------------------------------------------------------
// Gather + weighted sum: block = (b,h) x 16 consecutive l values (L1 reuse).
// 16 threads per tuple, float4 gathers.
// ---------------------------------------------------------------------------
__global__ __launch_bounds__(256) void gather_kernel(
    const float* __restrict__ w, float* __restrict__ out)
{
    const int blk = blockIdx.x;
    const int bh = blk >> 7;             // / (LEN/16 = 128)
    const int l  = ((blk & 127) << 4) + (threadIdx.x >> 4);
    const int b = bh / NH, h = bh % NH;
    const int t = (b * LEN + l) * NH + h;
    const int d4 = (threadIdx.x & 15) * 4;

    const int* fp = g_fm + (size_t)t * RR;
    const int* bp = g_bm + (size_t)t * RR;
    const float* wf = w + h * 2 * RR;

    const float* vb = g_V1 + (size_t)b * LEN * NN + h * HD + d4;

    float ax = 0.f, ay = 0.f, az = 0.f, aw = 0.f;
#pragma unroll
    for (int r = 0; r < RR; r++) {
        int i1 = __ldg(fp + r);
        int i2 = __ldg(bp + r);
        float w1 = __ldg(wf + r);
        float w2 = __ldg(wf + RR + r);
        float4 v1 = *(const float4*)(vb + (size_t)i1 * NN);
        float4 v2 = *(const float4*)(vb + (size_t)i2 * NN);
        ax = fmaf(w1, v1.x, fmaf(w2, v2.x, ax));
        ay = fmaf(w1, v1.y, fmaf(w2, v2.y, ay));
        az = fmaf(w1, v1.z, fmaf(w2, v2.z, az));
        aw = fmaf(w1, v1.w, fmaf(w2, v2.w, aw));
    }
    *(float4*)(out + (size_t)t * HD + d4) = make_float4(ax, ay, az, aw);
}

// ---------------------------------------------------------------------------
extern "C" void kernel_launch(void* const* d_in, const int* in_sizes, int n_in,
                              void* d_out, int out_size)
{
    const float* hidden = (const float*)d_in[0];
    const float* K1w    = (const float*)d_in[1];
    const float* K1b    = (const float*)d_in[2];
    const float* V1w    = (const float*)d_in[3];
    const float* V1b    = (const float*)d_in[4];
    const float* RH     = (const float*)d_in[5];
    const float* bw     = (const float*)d_in[6];
    float* out = (float*)d_out;

    cudaFuncSetAttribute(fused_gemm_kernel,
                         cudaFuncAttributeMaxDynamicSharedMemorySize, SM_TOTAL);

    // 1) Split fp32 -> fp16 hi/lo (weights also transposed to [n][k])
    convA_kernel<<<(MM * KK) / 1024, 256>>>(hidden);
    {
        dim3 tg(NN / 32, KK / 32), tb(32, 8);
        convW_kernel<0><<<tg, tb>>>(K1w);
        convW_kernel<1><<<tg, tb>>>(V1w);
    }

    // 2) Fused tensor-core GEMM, BM=64, 2 CTAs/SM, SMSP-balanced K3/V2 passes
    {
        dim3 gg(NH, MM / 64);  // (12, 128) = 1536 CTAs
        fused_gemm_kernel<<<gg, 256, SM_TOTAL>>>(K1b, V1b, RH);
    }

    // 3) Mask scan -> index tables
    scan_kernel<<<BSZ * NH, 256>>>();

    // 4) Gather + weighted sum (l-local blocks)
    gather_kernel<<<BSZ * NH * (LEN / 16), 256>>>(bw, out);
}

// round 13
// speedup vs baseline: 1.0928x; 1.0928x over previous
#include <cuda_runtime.h>
#include <cuda_fp16.h>
#include <cstdint>

// Problem constants
#define BSZ 4
#define LEN 2048
#define NH  12
#define HD  64
#define RR  16
#define HID 768
#define MM  (BSZ*LEN)   // 8192
#define NN  (NH*HD)     // 768
#define KK  HID         // 768

// ---------------------------------------------------------------------------
// Scratch (__device__ globals; allocation is forbidden)
// ---------------------------------------------------------------------------
__device__ __align__(16) __half g_Ahi[(size_t)MM * KK];
__device__ __align__(16) __half g_Alo[(size_t)MM * KK];
__device__ __align__(16) __half g_WhiK[(size_t)NN * KK];   // [n][k]
__device__ __align__(16) __half g_WloK[(size_t)NN * KK];
__device__ __align__(16) __half g_WhiV[(size_t)NN * KK];
__device__ __align__(16) __half g_WloV[(size_t)NN * KK];
__device__ __align__(16) __half g_V1[(size_t)MM * NN];     // fp16 V1 (halves gather lines)
__device__ __align__(16) float g_dot[(size_t)MM * NH];
__device__ __align__(16) int   g_fm[(size_t)MM * NH * RR];
__device__ __align__(16) int   g_bm[(size_t)MM * NH * RR];

// ---------------------------------------------------------------------------
// Baseline-PTX helpers (sm_80+: mma.sync / ldmatrix / cp.async — NO tcgen05)
// ---------------------------------------------------------------------------
__device__ __forceinline__ uint32_t smem_u32(const void* p) {
    uint32_t a;
    asm("{ .reg .u64 t; cvta.to.shared.u64 t, %1; cvt.u32.u64 %0, t; }"
        : "=r"(a) : "l"(p));
    return a;
}

__device__ __forceinline__ void cp16(uint32_t dst, const void* src) {
    asm volatile("cp.async.cg.shared.global [%0], [%1], 16;"
                 :: "r"(dst), "l"(src));
}
__device__ __forceinline__ void cp_commit() {
    asm volatile("cp.async.commit_group;");
}
template<int N> __device__ __forceinline__ void cp_wait() {
    asm volatile("cp.async.wait_group %0;" :: "n"(N));
}

__device__ __forceinline__ void ldsm4(uint32_t* r, uint32_t addr) {
    asm volatile("ldmatrix.sync.aligned.m8n8.x4.shared.b16 {%0,%1,%2,%3}, [%4];"
                 : "=r"(r[0]), "=r"(r[1]), "=r"(r[2]), "=r"(r[3]) : "r"(addr));
}

__device__ __forceinline__ void mma16816(float* c, const uint32_t* a,
                                         uint32_t b0, uint32_t b1) {
    asm volatile(
        "mma.sync.aligned.m16n8k16.row.col.f32.f16.f16.f32 "
        "{%0,%1,%2,%3}, {%4,%5,%6,%7}, {%8,%9}, {%0,%1,%2,%3};"
        : "+f"(c[0]), "+f"(c[1]), "+f"(c[2]), "+f"(c[3])
        : "r"(a[0]), "r"(a[1]), "r"(a[2]), "r"(a[3]), "r"(b0), "r"(b1));
}

// XOR-swizzled smem address: 128B rows, 16B segments, seg ^= (row & 7)
__device__ __forceinline__ uint32_t swz(int row, int seg) {
    return (uint32_t)(row * 128 + (((seg) ^ (row & 7)) << 4));
}

// ---------------------------------------------------------------------------
// Split-conversion kernels (fp32 -> fp16 hi + fp16 lo)
// ---------------------------------------------------------------------------
__device__ __forceinline__ uint32_t pack_h2(__half a, __half b) {
    return ((uint32_t)__half_as_ushort(b) << 16) | (uint32_t)__half_as_ushort(a);
}

__global__ __launch_bounds__(256) void convA_kernel(const float* __restrict__ A) {
    size_t i = ((size_t)blockIdx.x * 256 + threadIdx.x) * 4;
    float4 v = *(const float4*)(A + i);
    __half h0 = __float2half(v.x), h1 = __float2half(v.y);
    __half h2 = __float2half(v.z), h3 = __float2half(v.w);
    __half l0 = __float2half(v.x - __half2float(h0));
    __half l1 = __float2half(v.y - __half2float(h1));
    __half l2 = __float2half(v.z - __half2float(h2));
    __half l3 = __float2half(v.w - __half2float(h3));
    uint2 ph = make_uint2(pack_h2(h0, h1), pack_h2(h2, h3));
    uint2 pl = make_uint2(pack_h2(l0, l1), pack_h2(l2, l3));
    *(uint2*)((char*)g_Ahi + i * 2) = ph;
    *(uint2*)((char*)g_Alo + i * 2) = pl;
}

// Transpose W [k][n] -> [n][k], split hi/lo. WHICH==0 -> K weights, 1 -> V.
template<int WHICH>
__global__ void convW_kernel(const float* __restrict__ W) {
    __shared__ float t[32][33];
    int bx = blockIdx.x * 32;  // n tile
    int by = blockIdx.y * 32;  // k tile
    int tx = threadIdx.x, ty = threadIdx.y;
#pragma unroll
    for (int j = 0; j < 4; j++) {
        int r = ty + j * 8;
        t[r][tx] = W[(size_t)(by + r) * NN + bx + tx];
    }
    __syncthreads();
#pragma unroll
    for (int j = 0; j < 4; j++) {
        int r = ty + j * 8;
        float x = t[tx][r];  // = W[by+tx][bx+r]
        __half h = __float2half(x);
        __half l = __float2half(x - __half2float(h));
        size_t o = (size_t)(bx + r) * KK + by + tx;
        if (WHICH == 0) { g_WhiK[o] = h; g_WloK[o] = l; }
        else            { g_WhiV[o] = h; g_WloV[o] = l; }
    }
}

// ---------------------------------------------------------------------------
// FUSED mma.sync GEMM, fp16 3-pass split (symmetric K and V) — exact R11
// config (136.3 us proven), except V1 is stored as fp16.
// BM=64, BN=128 (cols 0-63 = K head, 64-127 = V head), BK=64.
// 256 threads = 8 warps (2m x 4n), warp tile 32x32.
// 2-stage double buffer, 96KB/CTA -> 2 CTAs/SM.
// ---------------------------------------------------------------------------
#define OFF_AH 0
#define OFF_AL 8192
#define OFF_BH 16384
#define OFF_BL 32768
#define STAGE  49152
#define NSTAGE 2
#define SM_TOTAL (NSTAGE * STAGE)   // 96 KB
#define NCHUNK (KK / 64)            // 12

__global__ __launch_bounds__(256, 2) void fused_gemm_kernel(
    const float* __restrict__ Kb, const float* __restrict__ Vb,
    const float* __restrict__ RH)
{
    extern __shared__ char smem[];
    __shared__ float sdot[64];
    const uint32_t sb = smem_u32(smem);

    const int tid = threadIdx.x;
    const int lane = tid & 31;
    const int wid = tid >> 5;
    const int nw = wid & 3;   // n warp col (0-1: K head, 2-3: V head)
    const int mw = wid >> 2;  // m warp row (0-1, 32 rows each)

    const int head = blockIdx.x;
    const int n0 = head * 64;
    const int m0 = blockIdx.y * 64;

    if (tid < 64) sdot[tid] = 0.f;   // visible by first loop barrier

    float acc[2][4][4];
#pragma unroll
    for (int i = 0; i < 2; i++)
#pragma unroll
        for (int j = 0; j < 4; j++)
#pragma unroll
            for (int q = 0; q < 4; q++) acc[i][j][q] = 0.f;

    auto load_chunk = [&](int c) {
        if (c < NCHUNK) {
            const int kt = c * 64;
            const uint32_t stb = sb + (c & 1) * STAGE;
            // A: 64 rows x 8 segs = 512 positions, hi+lo
#pragma unroll
            for (int i = 0; i < 2; i++) {
                int p = tid + i * 256;
                int row = p >> 3, seg = p & 7;
                uint32_t so = swz(row, seg);
                size_t ga = (size_t)(m0 + row) * KK + kt + seg * 8;
                cp16(stb + OFF_AH + so, g_Ahi + ga);
                cp16(stb + OFF_AL + so, g_Alo + ga);
            }
            // B: 128 rows x 8 segs = 1024 positions, hi+lo
#pragma unroll
            for (int i = 0; i < 4; i++) {
                int p = tid + i * 256;
                int row = p >> 3, seg = p & 7;
                uint32_t so = swz(row, seg);
                const __half* bh;
                const __half* bl;
                int grow;
                if (row < 64) { bh = g_WhiK; bl = g_WloK; grow = n0 + row; }
                else          { bh = g_WhiV; bl = g_WloV; grow = n0 + row - 64; }
                size_t gb = (size_t)grow * KK + kt + seg * 8;
                cp16(stb + OFF_BH + so, bh + gb);
                cp16(stb + OFF_BL + so, bl + gb);
            }
        }
        cp_commit();
    };

    load_chunk(0);

    for (int c = 0; c < NCHUNK; c++) {
        load_chunk(c + 1);          // into stage (c+1)&1 (freed by prev trailing barrier)
        cp_wait<1>();               // stage c complete
        __syncthreads();

        const uint32_t stb = sb + (c & 1) * STAGE;
#pragma unroll
        for (int ks = 0; ks < 4; ks++) {
            uint32_t ah[2][4], al[2][4], bh[2][4], bl[2][4];
#pragma unroll
            for (int mi = 0; mi < 2; mi++) {
                int row = mw * 32 + mi * 16 + (lane & 15);
                int seg = ks * 2 + (lane >> 4);
                uint32_t ao = swz(row, seg);
                ldsm4(ah[mi], stb + OFF_AH + ao);
                ldsm4(al[mi], stb + OFF_AL + ao);
            }
#pragma unroll
            for (int nt = 0; nt < 2; nt++) {
                int row = nw * 32 + nt * 16 + (lane & 7) + ((lane >> 4) << 3);
                int seg = ks * 2 + ((lane >> 3) & 1);
                uint32_t bo = swz(row, seg);
                ldsm4(bh[nt], stb + OFF_BH + bo);
                ldsm4(bl[nt], stb + OFF_BL + bo);
            }
            // Pass-major: 8 independent HMMAs per pass
#pragma unroll
            for (int mi = 0; mi < 2; mi++)
#pragma unroll
                for (int nj = 0; nj < 4; nj++) {
                    const int nt = nj >> 1, rb = (nj & 1) * 2;
                    mma16816(acc[mi][nj], ah[mi], bh[nt][rb], bh[nt][rb + 1]);
                }
#pragma unroll
            for (int mi = 0; mi < 2; mi++)
#pragma unroll
                for (int nj = 0; nj < 4; nj++) {
                    const int nt = nj >> 1, rb = (nj & 1) * 2;
                    mma16816(acc[mi][nj], al[mi], bh[nt][rb], bh[nt][rb + 1]);
                }
#pragma unroll
            for (int mi = 0; mi < 2; mi++)
#pragma unroll
                for (int nj = 0; nj < 4; nj++) {
                    const int nt = nj >> 1, rb = (nj & 1) * 2;
                    mma16816(acc[mi][nj], ah[mi], bl[nt][rb], bl[nt][rb + 1]);
                }
        }
        __syncthreads();   // stage c free before load(c+2) overwrites it
    }

    // ---- epilogue ----
    const int rrow = lane >> 2;
    const int cq = (lane & 3) * 2;

    if (nw < 2) {
        // K path: dot(relu(K1 + Kb), RH) per row
#pragma unroll
        for (int mi = 0; mi < 2; mi++) {
            float s0 = 0.f, s1 = 0.f;
#pragma unroll
            for (int nj = 0; nj < 4; nj++) {
                const int n = n0 + nw * 32 + nj * 8 + cq;
                const float b0v = Kb[n], b1v = Kb[n + 1];
                const float rh0 = RH[n], rh1 = RH[n + 1];
                s0 += fmaxf(acc[mi][nj][0] + b0v, 0.f) * rh0
                    + fmaxf(acc[mi][nj][1] + b1v, 0.f) * rh1;
                s1 += fmaxf(acc[mi][nj][2] + b0v, 0.f) * rh0
                    + fmaxf(acc[mi][nj][3] + b1v, 0.f) * rh1;
            }
            s0 += __shfl_xor_sync(0xffffffffu, s0, 1);
            s0 += __shfl_xor_sync(0xffffffffu, s0, 2);
            s1 += __shfl_xor_sync(0xffffffffu, s1, 1);
            s1 += __shfl_xor_sync(0xffffffffu, s1, 2);
            if ((lane & 3) == 0) {
                atomicAdd(&sdot[mw * 32 + mi * 16 + rrow], s0);
                atomicAdd(&sdot[mw * 32 + mi * 16 + rrow + 8], s1);
            }
        }
    } else {
        // V path: store relu(V1 + Vb) as fp16 (packed half2)
#pragma unroll
        for (int mi = 0; mi < 2; mi++) {
            const int r0 = m0 + mw * 32 + mi * 16 + rrow;
#pragma unroll
            for (int nj = 0; nj < 4; nj++) {
                const int n = n0 + (nw - 2) * 32 + nj * 8 + cq;
                const float b0v = Vb[n], b1v = Vb[n + 1];
                uint32_t p0 = pack_h2(__float2half(fmaxf(acc[mi][nj][0] + b0v, 0.f)),
                                      __float2half(fmaxf(acc[mi][nj][1] + b1v, 0.f)));
                uint32_t p1 = pack_h2(__float2half(fmaxf(acc[mi][nj][2] + b0v, 0.f)),
                                      __float2half(fmaxf(acc[mi][nj][3] + b1v, 0.f)));
                *(uint32_t*)&g_V1[(size_t)r0 * NN + n] = p0;
                *(uint32_t*)&g_V1[(size_t)(r0 + 8) * NN + n] = p1;
            }
        }
    }
    __syncthreads();
    if (tid < 64)
        g_dot[(size_t)(m0 + tid) * NH + head] = sdot[tid];
}

// ---------------------------------------------------------------------------
// Scan kernel (per (b,h)): prefix-count + event list -> fm/bm index tables
// (R6-proven version, unchanged)
// ---------------------------------------------------------------------------
__global__ __launch_bounds__(256) void scan_kernel()
{
    const int bh = blockIdx.x;
    const int b = bh / NH, h = bh % NH;

    __shared__ int s_cnt[LEN];
    __shared__ int s_e[LEN];
    __shared__ int s_wsum[8];

    const int tid = threadIdx.x;
    const int base = tid * 8;

    int c[8];
    unsigned mbits = 0;
    int run = 0;
#pragma unroll
    for (int q = 0; q < 8; q++) {
        int l = base + q;
        bool m = (l >= 1) && (g_dot[(size_t)(b * LEN + l) * NH + h] > 0.5f);
        if (m) { mbits |= 1u << q; run++; }
        c[q] = run;
    }

    const int lane = tid & 31, wd = tid >> 5;
    int v = run;
#pragma unroll
    for (int o = 1; o < 32; o <<= 1) {
        int nv = __shfl_up_sync(0xffffffffu, v, o);
        if (lane >= o) v += nv;
    }
    if (lane == 31) s_wsum[wd] = v;
    __syncthreads();
    int wpre = 0;
    for (int w = 0; w < wd; w++) wpre += s_wsum[w];
    const int excl = wpre + v - run;

#pragma unroll
    for (int q = 0; q < 8; q++) {
        s_cnt[base + q] = excl + c[q];
        if (mbits & (1u << q)) s_e[excl + c[q] - 1] = base + q;
    }
    __syncthreads();

    const int E = s_cnt[LEN - 1];

    for (int l = tid; l < LEN; l += 256) {
        int cl = s_cnt[l];
        int cp = (l > 0) ? s_cnt[l - 1] : 0;
        int fo[RR], bo[RR];
#pragma unroll
        for (int r = 0; r < RR; r++) {
            fo[r] = (cl > r) ? s_e[cl - 1 - r] : 0;
            bo[r] = (l > 0 && cp + r < E) ? s_e[cp + r] : 0;
        }
        size_t off = ((size_t)(b * LEN + l) * NH + h) * RR;
#pragma unroll
        for (int r4 = 0; r4 < RR; r4 += 4) {
            *(int4*)&g_fm[off + r4] = make_int4(fo[r4], fo[r4+1], fo[r4+2], fo[r4+3]);
            *(int4*)&g_bm[off + r4] = make_int4(bo[r4], bo[r4+1], bo[r4+2], bo[r4+3]);
        }
    }
}

// ---------------------------------------------------------------------------
// Gather + weighted sum over fp16 V1.
// Block = (b,h) x 16 consecutive l values; 16 threads per tuple.
// Indices + weights loaded ONCE per lane and shfl-broadcast (cuts LDG issues
// per thread 96 -> 34). Each thread loads 4 halves (8B) per gathered row.
// ---------------------------------------------------------------------------
__global__ __launch_bounds__(256) void gather_kernel(
    const float* __restrict__ w, float* __restrict__ out)
{
    const int blk = blockIdx.x;
    const int bh = blk >> 7;             // / (LEN/16 = 128)
    const int l  = ((blk & 127) << 4) + (threadIdx.x >> 4);
    const int b = bh / NH, h = bh % NH;
    const int t = (b * LEN + l) * NH + h;
    const int lane = threadIdx.x & 31;
    const int r0 = lane & 15;            // this lane preloads r = r0
    const int d4 = (lane & 15) * 4;      // half index within head dim

    // Per-lane preload of one (fm, bm, wF, wB) quartet for its own tuple
    const int myf = __ldg(&g_fm[(size_t)t * RR + r0]);
    const int myb = __ldg(&g_bm[(size_t)t * RR + r0]);
    const float mwf = __ldg(&w[h * 2 * RR + r0]);
    const float mwb = __ldg(&w[h * 2 * RR + RR + r0]);

    const __half* vb = g_V1 + (size_t)b * LEN * NN + h * HD + d4;

    float ax = 0.f, ay = 0.f, az = 0.f, aw = 0.f;
#pragma unroll
    for (int r = 0; r < RR; r++) {
        const int src = (lane & 16) | r;   // same half-warp (same tuple), lane r
        int i1 = __shfl_sync(0xffffffffu, myf, src);
        int i2 = __shfl_sync(0xffffffffu, myb, src);
        float w1 = __shfl_sync(0xffffffffu, mwf, src);
        float w2 = __shfl_sync(0xffffffffu, mwb, src);
        uint2 p1 = *(const uint2*)(vb + (size_t)i1 * NN);
        uint2 p2 = *(const uint2*)(vb + (size_t)i2 * NN);
        float2 a01 = __half22float2(*(const __half2*)&p1.x);
        float2 a23 = __half22float2(*(const __half2*)&p1.y);
        float2 b01 = __half22float2(*(const __half2*)&p2.x);
        float2 b23 = __half22float2(*(const __half2*)&p2.y);
        ax = fmaf(w1, a01.x, fmaf(w2, b01.x, ax));
        ay = fmaf(w1, a01.y, fmaf(w2, b01.y, ay));
        az = fmaf(w1, a23.x, fmaf(w2, b23.x, az));
        aw = fmaf(w1, a23.y, fmaf(w2, b23.y, aw));
    }
    *(float4*)(out + (size_t)t * HD + d4) = make_float4(ax, ay, az, aw);
}

// ---------------------------------------------------------------------------
extern "C" void kernel_launch(void* const* d_in, const int* in_sizes, int n_in,
                              void* d_out, int out_size)
{
    const float* hidden = (const float*)d_in[0];
    const float* K1w    = (const float*)d_in[1];
    const float* K1b    = (const float*)d_in[2];
    const float* V1w    = (const float*)d_in[3];
    const float* V1b    = (const float*)d_in[4];
    const float* RH     = (const float*)d_in[5];
    const float* bw     = (const float*)d_in[6];
    float* out = (float*)d_out;

    cudaFuncSetAttribute(fused_gemm_kernel,
                         cudaFuncAttributeMaxDynamicSharedMemorySize, SM_TOTAL);

    // 1) Split fp32 -> fp16 hi/lo (weights also transposed to [n][k])
    convA_kernel<<<(MM * KK) / 1024, 256>>>(hidden);
    {
        dim3 tg(NN / 32, KK / 32), tb(32, 8);
        convW_kernel<0><<<tg, tb>>>(K1w);
        convW_kernel<1><<<tg, tb>>>(V1w);
    }

    // 2) Fused tensor-core GEMM (exact R11 config; fp16 V1 store)
    {
        dim3 gg(NH, MM / 64);  // (12, 128) = 1536 CTAs
        fused_gemm_kernel<<<gg, 256, SM_TOTAL>>>(K1b, V1b, RH);
    }

    // 3) Mask scan -> index tables
    scan_kernel<<<BSZ * NH, 256>>>();

    // 4) Gather + weighted sum (fp16 rows, shfl-broadcast indices)
    gather_kernel<<<BSZ * NH * (LEN / 16), 256>>>(bw, out);
}

// round 14
// speedup vs baseline: 1.2108x; 1.1080x over previous
#include <cuda_runtime.h>
#include <cuda_fp16.h>
#include <cstdint>

// Problem constants
#define BSZ 4
#define LEN 2048
#define NH  12
#define HD  64
#define RR  16
#define HID 768
#define MM  (BSZ*LEN)   // 8192
#define NN  (NH*HD)     // 768
#define KK  HID         // 768

// ---------------------------------------------------------------------------
// Scratch (__device__ globals; allocation is forbidden)
// ---------------------------------------------------------------------------
__device__ __align__(16) __half g_Ahi[(size_t)MM * KK];
__device__ __align__(16) __half g_Alo[(size_t)MM * KK];
__device__ __align__(16) __half g_WhiK[(size_t)NN * KK];   // [n][k]
__device__ __align__(16) __half g_WloK[(size_t)NN * KK];
__device__ __align__(16) __half g_WhiV[(size_t)NN * KK];
__device__ __align__(16) __half g_WloV[(size_t)NN * KK];
__device__ __align__(16) __half g_V1[(size_t)MM * NN];     // fp16 V1
__device__ __align__(16) float g_dot[(size_t)MM * NH];
// Compact mask representation (scalar access ONLY — no vector hazards)
__device__ int g_cnt[(size_t)BSZ * NH * LEN];
__device__ int g_e[(size_t)BSZ * NH * LEN];
__device__ int g_E[BSZ * NH];

// ---------------------------------------------------------------------------
// Baseline-PTX helpers (sm_80+: mma.sync / ldmatrix / cp.async — NO tcgen05)
// ---------------------------------------------------------------------------
__device__ __forceinline__ uint32_t smem_u32(const void* p) {
    uint32_t a;
    asm("{ .reg .u64 t; cvta.to.shared.u64 t, %1; cvt.u32.u64 %0, t; }"
        : "=r"(a) : "l"(p));
    return a;
}

__device__ __forceinline__ void cp16(uint32_t dst, const void* src) {
    asm volatile("cp.async.cg.shared.global [%0], [%1], 16;"
                 :: "r"(dst), "l"(src));
}
__device__ __forceinline__ void cp_commit() {
    asm volatile("cp.async.commit_group;");
}
template<int N> __device__ __forceinline__ void cp_wait() {
    asm volatile("cp.async.wait_group %0;" :: "n"(N));
}

__device__ __forceinline__ void ldsm4(uint32_t* r, uint32_t addr) {
    asm volatile("ldmatrix.sync.aligned.m8n8.x4.shared.b16 {%0,%1,%2,%3}, [%4];"
                 : "=r"(r[0]), "=r"(r[1]), "=r"(r[2]), "=r"(r[3]) : "r"(addr));
}

__device__ __forceinline__ void mma16816(float* c, const uint32_t* a,
                                         uint32_t b0, uint32_t b1) {
    asm volatile(
        "mma.sync.aligned.m16n8k16.row.col.f32.f16.f16.f32 "
        "{%0,%1,%2,%3}, {%4,%5,%6,%7}, {%8,%9}, {%0,%1,%2,%3};"
        : "+f"(c[0]), "+f"(c[1]), "+f"(c[2]), "+f"(c[3])
        : "r"(a[0]), "r"(a[1]), "r"(a[2]), "r"(a[3]), "r"(b0), "r"(b1));
}

// XOR-swizzled smem address: 128B rows, 16B segments, seg ^= (row & 7)
__device__ __forceinline__ uint32_t swz(int row, int seg) {
    return (uint32_t)(row * 128 + (((seg) ^ (row & 7)) << 4));
}

// ---------------------------------------------------------------------------
// Split-conversion kernels (fp32 -> fp16 hi + fp16 lo)
// ---------------------------------------------------------------------------
__device__ __forceinline__ uint32_t pack_h2(__half a, __half b) {
    return ((uint32_t)__half_as_ushort(b) << 16) | (uint32_t)__half_as_ushort(a);
}

__global__ __launch_bounds__(256) void convA_kernel(const float* __restrict__ A) {
    size_t i = ((size_t)blockIdx.x * 256 + threadIdx.x) * 4;
    float4 v = *(const float4*)(A + i);
    __half h0 = __float2half(v.x), h1 = __float2half(v.y);
    __half h2 = __float2half(v.z), h3 = __float2half(v.w);
    __half l0 = __float2half(v.x - __half2float(h0));
    __half l1 = __float2half(v.y - __half2float(h1));
    __half l2 = __float2half(v.z - __half2float(h2));
    __half l3 = __float2half(v.w - __half2float(h3));
    uint2 ph = make_uint2(pack_h2(h0, h1), pack_h2(h2, h3));
    uint2 pl = make_uint2(pack_h2(l0, l1), pack_h2(l2, l3));
    *(uint2*)((char*)g_Ahi + i * 2) = ph;
    *(uint2*)((char*)g_Alo + i * 2) = pl;
}

// Transpose W [k][n] -> [n][k], split hi/lo. blockIdx.z: 0 -> K, 1 -> V.
__global__ void convW_kernel(const float* __restrict__ WK,
                             const float* __restrict__ WV) {
    __shared__ float t[32][33];
    const float* W = (blockIdx.z == 0) ? WK : WV;
    int bx = blockIdx.x * 32;  // n tile
    int by = blockIdx.y * 32;  // k tile
    int tx = threadIdx.x, ty = threadIdx.y;
#pragma unroll
    for (int j = 0; j < 4; j++) {
        int r = ty + j * 8;
        t[r][tx] = W[(size_t)(by + r) * NN + bx + tx];
    }
    __syncthreads();
#pragma unroll
    for (int j = 0; j < 4; j++) {
        int r = ty + j * 8;
        float x = t[tx][r];  // = W[by+tx][bx+r]
        __half h = __float2half(x);
        __half l = __float2half(x - __half2float(h));
        size_t o = (size_t)(bx + r) * KK + by + tx;
        if (blockIdx.z == 0) { g_WhiK[o] = h; g_WloK[o] = l; }
        else                 { g_WhiV[o] = h; g_WloV[o] = l; }
    }
}

// ---------------------------------------------------------------------------
// FUSED mma.sync GEMM, fp16 3-pass split — exact R13 config (135.4 us).
// BM=64, BN=128 (cols 0-63 = K head, 64-127 = V head), BK=64.
// 256 threads = 8 warps (2m x 4n), warp tile 32x32.
// 2-stage double buffer, 96KB/CTA -> 2 CTAs/SM. fp16 V1 store.
// ---------------------------------------------------------------------------
#define OFF_AH 0
#define OFF_AL 8192
#define OFF_BH 16384
#define OFF_BL 32768
#define STAGE  49152
#define NSTAGE 2
#define SM_TOTAL (NSTAGE * STAGE)   // 96 KB
#define NCHUNK (KK / 64)            // 12

__global__ __launch_bounds__(256, 2) void fused_gemm_kernel(
    const float* __restrict__ Kb, const float* __restrict__ Vb,
    const float* __restrict__ RH)
{
    extern __shared__ char smem[];
    __shared__ float sdot[64];
    const uint32_t sb = smem_u32(smem);

    const int tid = threadIdx.x;
    const int lane = tid & 31;
    const int wid = tid >> 5;
    const int nw = wid & 3;   // n warp col (0-1: K head, 2-3: V head)
    const int mw = wid >> 2;  // m warp row (0-1, 32 rows each)

    const int head = blockIdx.x;
    const int n0 = head * 64;
    const int m0 = blockIdx.y * 64;

    if (tid < 64) sdot[tid] = 0.f;

    float acc[2][4][4];
#pragma unroll
    for (int i = 0; i < 2; i++)
#pragma unroll
        for (int j = 0; j < 4; j++)
#pragma unroll
            for (int q = 0; q < 4; q++) acc[i][j][q] = 0.f;

    auto load_chunk = [&](int c) {
        if (c < NCHUNK) {
            const int kt = c * 64;
            const uint32_t stb = sb + (c & 1) * STAGE;
#pragma unroll
            for (int i = 0; i < 2; i++) {
                int p = tid + i * 256;
                int row = p >> 3, seg = p & 7;
                uint32_t so = swz(row, seg);
                size_t ga = (size_t)(m0 + row) * KK + kt + seg * 8;
                cp16(stb + OFF_AH + so, g_Ahi + ga);
                cp16(stb + OFF_AL + so, g_Alo + ga);
            }
#pragma unroll
            for (int i = 0; i < 4; i++) {
                int p = tid + i * 256;
                int row = p >> 3, seg = p & 7;
                uint32_t so = swz(row, seg);
                const __half* bh;
                const __half* bl;
                int grow;
                if (row < 64) { bh = g_WhiK; bl = g_WloK; grow = n0 + row; }
                else          { bh = g_WhiV; bl = g_WloV; grow = n0 + row - 64; }
                size_t gb = (size_t)grow * KK + kt + seg * 8;
                cp16(stb + OFF_BH + so, bh + gb);
                cp16(stb + OFF_BL + so, bl + gb);
            }
        }
        cp_commit();
    };

    load_chunk(0);

    for (int c = 0; c < NCHUNK; c++) {
        load_chunk(c + 1);
        cp_wait<1>();
        __syncthreads();

        const uint32_t stb = sb + (c & 1) * STAGE;
#pragma unroll
        for (int ks = 0; ks < 4; ks++) {
            uint32_t ah[2][4], al[2][4], bh[2][4], bl[2][4];
#pragma unroll
            for (int mi = 0; mi < 2; mi++) {
                int row = mw * 32 + mi * 16 + (lane & 15);
                int seg = ks * 2 + (lane >> 4);
                uint32_t ao = swz(row, seg);
                ldsm4(ah[mi], stb + OFF_AH + ao);
                ldsm4(al[mi], stb + OFF_AL + ao);
            }
#pragma unroll
            for (int nt = 0; nt < 2; nt++) {
                int row = nw * 32 + nt * 16 + (lane & 7) + ((lane >> 4) << 3);
                int seg = ks * 2 + ((lane >> 3) & 1);
                uint32_t bo = swz(row, seg);
                ldsm4(bh[nt], stb + OFF_BH + bo);
                ldsm4(bl[nt], stb + OFF_BL + bo);
            }
#pragma unroll
            for (int mi = 0; mi < 2; mi++)
#pragma unroll
                for (int nj = 0; nj < 4; nj++) {
                    const int nt = nj >> 1, rb = (nj & 1) * 2;
                    mma16816(acc[mi][nj], ah[mi], bh[nt][rb], bh[nt][rb + 1]);
                }
#pragma unroll
            for (int mi = 0; mi < 2; mi++)
#pragma unroll
                for (int nj = 0; nj < 4; nj++) {
                    const int nt = nj >> 1, rb = (nj & 1) * 2;
                    mma16816(acc[mi][nj], al[mi], bh[nt][rb], bh[nt][rb + 1]);
                }
#pragma unroll
            for (int mi = 0; mi < 2; mi++)
#pragma unroll
                for (int nj = 0; nj < 4; nj++) {
                    const int nt = nj >> 1, rb = (nj & 1) * 2;
                    mma16816(acc[mi][nj], ah[mi], bl[nt][rb], bl[nt][rb + 1]);
                }
        }
        __syncthreads();
    }

    // ---- epilogue ----
    const int rrow = lane >> 2;
    const int cq = (lane & 3) * 2;

    if (nw < 2) {
#pragma unroll
        for (int mi = 0; mi < 2; mi++) {
            float s0 = 0.f, s1 = 0.f;
#pragma unroll
            for (int nj = 0; nj < 4; nj++) {
                const int n = n0 + nw * 32 + nj * 8 + cq;
                const float b0v = Kb[n], b1v = Kb[n + 1];
                const float rh0 = RH[n], rh1 = RH[n + 1];
                s0 += fmaxf(acc[mi][nj][0] + b0v, 0.f) * rh0
                    + fmaxf(acc[mi][nj][1] + b1v, 0.f) * rh1;
                s1 += fmaxf(acc[mi][nj][2] + b0v, 0.f) * rh0
                    + fmaxf(acc[mi][nj][3] + b1v, 0.f) * rh1;
            }
            s0 += __shfl_xor_sync(0xffffffffu, s0, 1);
            s0 += __shfl_xor_sync(0xffffffffu, s0, 2);
            s1 += __shfl_xor_sync(0xffffffffu, s1, 1);
            s1 += __shfl_xor_sync(0xffffffffu, s1, 2);
            if ((lane & 3) == 0) {
                atomicAdd(&sdot[mw * 32 + mi * 16 + rrow], s0);
                atomicAdd(&sdot[mw * 32 + mi * 16 + rrow + 8], s1);
            }
        }
    } else {
#pragma unroll
        for (int mi = 0; mi < 2; mi++) {
            const int r0 = m0 + mw * 32 + mi * 16 + rrow;
#pragma unroll
            for (int nj = 0; nj < 4; nj++) {
                const int n = n0 + (nw - 2) * 32 + nj * 8 + cq;
                const float b0v = Vb[n], b1v = Vb[n + 1];
                uint32_t p0 = pack_h2(__float2half(fmaxf(acc[mi][nj][0] + b0v, 0.f)),
                                      __float2half(fmaxf(acc[mi][nj][1] + b1v, 0.f)));
                uint32_t p1 = pack_h2(__float2half(fmaxf(acc[mi][nj][2] + b0v, 0.f)),
                                      __float2half(fmaxf(acc[mi][nj][3] + b1v, 0.f)));
                *(uint32_t*)&g_V1[(size_t)r0 * NN + n] = p0;
                *(uint32_t*)&g_V1[(size_t)(r0 + 8) * NN + n] = p1;
            }
        }
    }
    __syncthreads();
    if (tid < 64)
        g_dot[(size_t)(m0 + tid) * NH + head] = sdot[tid];
}

// ---------------------------------------------------------------------------
// Scan kernel (per (b,h)): prefix-count + event list.
// Emits ONLY compact cnt[] / e[] / E (scalar stores — no fm/bm tables).
// ---------------------------------------------------------------------------
__global__ __launch_bounds__(256) void scan_kernel()
{
    const int bh = blockIdx.x;
    const int b = bh / NH, h = bh % NH;

    __shared__ int s_cnt[LEN];
    __shared__ int s_e[LEN];
    __shared__ int s_wsum[8];

    const int tid = threadIdx.x;
    const int base = tid * 8;

    int c[8];
    unsigned mbits = 0;
    int run = 0;
#pragma unroll
    for (int q = 0; q < 8; q++) {
        int l = base + q;
        bool m = (l >= 1) && (g_dot[(size_t)(b * LEN + l) * NH + h] > 0.5f);
        if (m) { mbits |= 1u << q; run++; }
        c[q] = run;
    }

    const int lane = tid & 31, wd = tid >> 5;
    int v = run;
#pragma unroll
    for (int o = 1; o < 32; o <<= 1) {
        int nv = __shfl_up_sync(0xffffffffu, v, o);
        if (lane >= o) v += nv;
    }
    if (lane == 31) s_wsum[wd] = v;
    __syncthreads();
    int wpre = 0;
    for (int w = 0; w < wd; w++) wpre += s_wsum[w];
    const int excl = wpre + v - run;

#pragma unroll
    for (int q = 0; q < 8; q++) {
        s_cnt[base + q] = excl + c[q];
        if (mbits & (1u << q)) s_e[excl + c[q] - 1] = base + q;
    }
    __syncthreads();

    const int E = s_cnt[LEN - 1];
    if (tid == 0) g_E[bh] = E;

    for (int l = tid; l < LEN; l += 256)
        g_cnt[(size_t)bh * LEN + l] = s_cnt[l];
    for (int j = tid; j < E; j += 256)
        g_e[(size_t)bh * LEN + j] = s_e[j];
}

// ---------------------------------------------------------------------------
// Gather + weighted sum over fp16 V1, indices reconstructed from cnt/e:
//   fo[r] = (cl > r) ? e[cl-1-r] : 0
//   bo[r] = (l > 0 && cp + r < E) ? e[cp+r] : 0
// Block = (b,h) x 16 consecutive l; 16 threads/tuple; lane r0 computes its
// own (i1,i2,wF,wB), then the half-warp shfl-broadcasts per r.
// ---------------------------------------------------------------------------
__global__ __launch_bounds__(256) void gather_kernel(
    const float* __restrict__ w, float* __restrict__ out)
{
    const int blk = blockIdx.x;
    const int bh = blk >> 7;             // / (LEN/16 = 128)
    const int l  = ((blk & 127) << 4) + (threadIdx.x >> 4);
    const int b = bh / NH, h = bh % NH;
    const int t = (b * LEN + l) * NH + h;
    const int lane = threadIdx.x & 31;
    const int r0 = lane & 15;
    const int d4 = (lane & 15) * 4;

    const int* cntp = g_cnt + (size_t)bh * LEN;
    const int* ev = g_e + (size_t)bh * LEN;
    const int E = __ldg(&g_E[bh]);
    const int cl = __ldg(cntp + l);
    const int cp = (l > 0) ? __ldg(cntp + l - 1) : 0;

    const int myf = (cl > r0) ? __ldg(ev + cl - 1 - r0) : 0;
    const int myb = (l > 0 && cp + r0 < E) ? __ldg(ev + cp + r0) : 0;
    const float mwf = __ldg(&w[h * 2 * RR + r0]);
    const float mwb = __ldg(&w[h * 2 * RR + RR + r0]);

    const __half* vb = g_V1 + (size_t)b * LEN * NN + h * HD + d4;

    float ax = 0.f, ay = 0.f, az = 0.f, aw = 0.f;
#pragma unroll
    for (int r = 0; r < RR; r++) {
        const int src = (lane & 16) | r;
        int i1 = __shfl_sync(0xffffffffu, myf, src);
        int i2 = __shfl_sync(0xffffffffu, myb, src);
        float w1 = __shfl_sync(0xffffffffu, mwf, src);
        float w2 = __shfl_sync(0xffffffffu, mwb, src);
        uint2 p1 = *(const uint2*)(vb + (size_t)i1 * NN);
        uint2 p2 = *(const uint2*)(vb + (size_t)i2 * NN);
        float2 a01 = __half22float2(*(const __half2*)&p1.x);
        float2 a23 = __half22float2(*(const __half2*)&p1.y);
        float2 b01 = __half22float2(*(const __half2*)&p2.x);
        float2 b23 = __half22float2(*(const __half2*)&p2.y);
        ax = fmaf(w1, a01.x, fmaf(w2, b01.x, ax));
        ay = fmaf(w1, a01.y, fmaf(w2, b01.y, ay));
        az = fmaf(w1, a23.x, fmaf(w2, b23.x, az));
        aw = fmaf(w1, a23.y, fmaf(w2, b23.y, aw));
    }
    *(float4*)(out + (size_t)t * HD + d4) = make_float4(ax, ay, az, aw);
}

// ---------------------------------------------------------------------------
extern "C" void kernel_launch(void* const* d_in, const int* in_sizes, int n_in,
                              void* d_out, int out_size)
{
    const float* hidden = (const float*)d_in[0];
    const float* K1w    = (const float*)d_in[1];
    const float* K1b    = (const float*)d_in[2];
    const float* V1w    = (const float*)d_in[3];
    const float* V1b    = (const float*)d_in[4];
    const float* RH     = (const float*)d_in[5];
    const float* bw     = (const float*)d_in[6];
    float* out = (float*)d_out;

    cudaFuncSetAttribute(fused_gemm_kernel,
                         cudaFuncAttributeMaxDynamicSharedMemorySize, SM_TOTAL);

    // 1) Split fp32 -> fp16 hi/lo (weights transposed to [n][k]); one convW launch
    convA_kernel<<<(MM * KK) / 1024, 256>>>(hidden);
    {
        dim3 tg(NN / 32, KK / 32, 2), tb(32, 8);
        convW_kernel<<<tg, tb>>>(K1w, V1w);
    }

    // 2) Fused tensor-core GEMM (R13 config)
    {
        dim3 gg(NH, MM / 64);  // (12, 128) = 1536 CTAs
        fused_gemm_kernel<<<gg, 256, SM_TOTAL>>>(K1b, V1b, RH);
    }

    // 3) Mask scan -> compact cnt/e/E
    scan_kernel<<<BSZ * NH, 256>>>();

    // 4) Gather + weighted sum (indices reconstructed from cnt/e)
    gather_kernel<<<BSZ * NH * (LEN / 16), 256>>>(bw, out);
}